// round 8
// baseline (speedup 1.0000x reference)
#include <cuda_runtime.h>
#include <cstdint>

#define Bb   16
#define H4   4096
#define KC   128           // k-rows per block
#define NKC  8             // k-chunks (1024 / KC)
#define NSPLIT 16          // NKC * 2 matrices
#define TPB  256
#define SK   16            // k-rows per pipeline stage (32 KB)
#define NST  (KC / SK)     // 8 stages
#define RS   4             // ring slots
#define JT   512           // columns per j-tile (2KB rows)
#define ROW_BYTES  (JT * 4)
#define STAGE_BYTES (SK * ROW_BYTES)
#define SMEM_BYTES (RS * SK * JT * 4 + KC * Bb * 4 + RS * 8)

// scratch: 128 float2-planes of [H4]; plane p = sp*8 + q holds {b=2q, b=2q+1}
__device__ float g_part[(size_t)NSPLIT * Bb * H4];   // 4 MB

__device__ __forceinline__ unsigned long long pack2(float lo, float hi) {
    unsigned long long r;
    asm("mov.b64 %0, {%1, %2};" : "=l"(r) : "f"(lo), "f"(hi));
    return r;
}
__device__ __forceinline__ unsigned long long fma2(unsigned long long a,
                                                   unsigned long long b,
                                                   unsigned long long c) {
    unsigned long long d;
    asm("fma.rn.f32x2 %0, %1, %2, %3;" : "=l"(d) : "l"(a), "l"(b), "l"(c));
    return d;
}
__device__ __forceinline__ uint32_t smem_u32(const void* p) {
    uint32_t a;
    asm("{ .reg .u64 t; cvta.to.shared.u64 t, %1; cvt.u32.u64 %0, t; }"
        : "=r"(a) : "l"(p));
    return a;
}
__device__ __forceinline__ void mbar_init(uint32_t mbar, uint32_t cnt) {
    asm volatile("mbarrier.init.shared.b64 [%0], %1;" :: "r"(mbar), "r"(cnt) : "memory");
}
__device__ __forceinline__ void mbar_expect_tx(uint32_t mbar, uint32_t bytes) {
    asm volatile("mbarrier.arrive.expect_tx.shared.b64 _, [%0], %1;"
                 :: "r"(mbar), "r"(bytes) : "memory");
}
__device__ __forceinline__ void mbar_wait(uint32_t mbar, uint32_t phase) {
    asm volatile(
        "{\n\t.reg .pred P;\n\t"
        "W_%=:\n\t"
        "mbarrier.try_wait.parity.acquire.cta.shared::cta.b64 P, [%0], %1, 0x989680;\n\t"
        "@P bra D_%=;\n\t"
        "bra W_%=;\n\t"
        "D_%=:\n\t}"
        :: "r"(mbar), "r"(phase) : "memory");
}
__device__ __forceinline__ void bulk_copy(uint32_t dst_smem, const void* src,
                                          uint32_t bytes, uint32_t mbar) {
    asm volatile(
        "cp.async.bulk.shared::cluster.global.mbarrier::complete_tx::bytes "
        "[%0], [%1], %2, [%3];"
        :: "r"(dst_smem), "l"(src), "r"(bytes), "r"(mbar) : "memory");
}

// ---------------------------------------------------------------------------
// Kernel 1: split-K GEMM partials, deep TMA-engine weight pipeline.
// grid = (8 j-tiles, 8 k-chunks, 2 matrices) = 128 blocks (1 wave), 256 thr.
// Ring of 4 x 32KB smem stages, all issued ahead -> ~96KB in flight / block.
// Per thread: 2 cols x 16 batches (8 f32x2 pairs); per k-row:
// 1 LDS.64 (w) + 4 broadcast LDS.128 (acts) + 16 FFMA2.
// ---------------------------------------------------------------------------
__global__ __launch_bounds__(TPB, 1) void gemm_part(
    const float* __restrict__ Wi, const float* __restrict__ Wh,
    const float* __restrict__ x,  const float* __restrict__ h)
{
    extern __shared__ char dsm[];
    float* wsm    = reinterpret_cast<float*>(dsm);            // RS*SK*JT floats
    float* sh_act = wsm + RS * SK * JT;                       // KC*Bb floats
    unsigned long long* mbar =
        reinterpret_cast<unsigned long long*>(sh_act + KC * Bb);

    const int jt  = blockIdx.x;            // 0..7
    const int kc  = blockIdx.y;            // 0..7
    const int mat = blockIdx.z;            // 0: Wi/x, 1: Wh/h
    const float* __restrict__ W   = mat ? Wh : Wi;
    const float* __restrict__ act = mat ? h  : x;
    const int k0  = kc * KC;
    const int tid = threadIdx.x;

    uint32_t mb[RS];
#pragma unroll
    for (int i = 0; i < RS; i++) mb[i] = smem_u32(&mbar[i]);
    const uint32_t wbase = smem_u32(wsm);
    const float* Wbase = W + (size_t)k0 * H4 + jt * JT;

    if (tid == 0) {
#pragma unroll
        for (int i = 0; i < RS; i++) mbar_init(mb[i], 1);
    }

    // stage activations: coalesced gmem read, smem scatter [k][b]
    for (int i = tid; i < Bb * KC; i += TPB) {
        int b = i >> 7;
        int k = i & (KC - 1);
        sh_act[k * Bb + b] = act[b * 1024 + k0 + k];
    }
    __syncthreads();

    // prologue: fill the whole ring (4 stages = 128 KB in flight)
    if (tid == 0) {
#pragma unroll
        for (int st = 0; st < RS; st++) {
            mbar_expect_tx(mb[st], STAGE_BYTES);
#pragma unroll
            for (int r = 0; r < SK; r++)
                bulk_copy(wbase + (st * SK + r) * ROW_BYTES,
                          Wbase + (size_t)(st * SK + r) * H4, ROW_BYTES, mb[st]);
        }
    }

    unsigned long long acc[2][8];          // [col][batch-pair]
#pragma unroll
    for (int c = 0; c < 2; c++)
#pragma unroll
        for (int q = 0; q < 8; q++) acc[c][q] = 0ull;

    for (int s = 0; s < NST; s++) {
        const int slot = s & (RS - 1);
        mbar_wait(mb[slot], (s >> 2) & 1);
        const float* wst = wsm + slot * SK * JT;

#pragma unroll
        for (int r = 0; r < SK; r++) {
            const int k = s * SK + r;
            float2 w = *reinterpret_cast<const float2*>(&wst[r * JT + tid * 2]);
            const float* ak = &sh_act[k * Bb];
            ulonglong2 A0 = *reinterpret_cast<const ulonglong2*>(ak);
            ulonglong2 A1 = *reinterpret_cast<const ulonglong2*>(ak + 4);
            ulonglong2 A2 = *reinterpret_cast<const ulonglong2*>(ak + 8);
            ulonglong2 A3 = *reinterpret_cast<const ulonglong2*>(ak + 12);
            unsigned long long w0 = pack2(w.x, w.x);
            unsigned long long w1 = pack2(w.y, w.y);
            acc[0][0] = fma2(w0, A0.x, acc[0][0]);
            acc[0][1] = fma2(w0, A0.y, acc[0][1]);
            acc[0][2] = fma2(w0, A1.x, acc[0][2]);
            acc[0][3] = fma2(w0, A1.y, acc[0][3]);
            acc[0][4] = fma2(w0, A2.x, acc[0][4]);
            acc[0][5] = fma2(w0, A2.y, acc[0][5]);
            acc[0][6] = fma2(w0, A3.x, acc[0][6]);
            acc[0][7] = fma2(w0, A3.y, acc[0][7]);
            acc[1][0] = fma2(w1, A0.x, acc[1][0]);
            acc[1][1] = fma2(w1, A0.y, acc[1][1]);
            acc[1][2] = fma2(w1, A1.x, acc[1][2]);
            acc[1][3] = fma2(w1, A1.y, acc[1][3]);
            acc[1][4] = fma2(w1, A2.x, acc[1][4]);
            acc[1][5] = fma2(w1, A2.y, acc[1][5]);
            acc[1][6] = fma2(w1, A3.x, acc[1][6]);
            acc[1][7] = fma2(w1, A3.y, acc[1][7]);
        }

        __syncthreads();                   // everyone done with this slot
        if (tid == 0 && s + RS < NST) {
            mbar_expect_tx(mb[slot], STAGE_BYTES);
#pragma unroll
            for (int r = 0; r < SK; r++)
                bulk_copy(wbase + (slot * SK + r) * ROW_BYTES,
                          Wbase + (size_t)((s + RS) * SK + r) * H4, ROW_BYTES, mb[slot]);
        }
    }

    // epilogue: coalesced STG.128 into per-(split, q) float2 planes
    const int sp = mat * NKC + kc;
    const int j0 = jt * JT + tid * 2;
#pragma unroll
    for (int q = 0; q < 8; q++) {
        float2* plane = reinterpret_cast<float2*>(g_part) + (size_t)(sp * 8 + q) * H4;
        *reinterpret_cast<ulonglong2*>(plane + j0) =
            make_ulonglong2(acc[0][q], acc[1][q]);
    }
}

// ---------------------------------------------------------------------------
// Kernel 2 (fused): reduce 16 partials + biases + LSTM gates -> out.
// 8192 threads: thread = (batch-pair q, column n); sums 4 gates x 16 splits
// (L2-resident float2 loads), applies gates for batches 2q, 2q+1.
// out = [h_new (B*H) | c_new (B*H)]
// ---------------------------------------------------------------------------
__global__ __launch_bounds__(256) void reduce_gates(
    const float* __restrict__ Wib, const float* __restrict__ Whb,
    const float* __restrict__ c,   float* __restrict__ out)
{
    int t = blockIdx.x * blockDim.x + threadIdx.x;   // 0..8191
    int q = t >> 10;                                  // 0..7
    int n = t & 1023;

    const float2* gp = reinterpret_cast<const float2*>(g_part);
    float2 sum[4];
#pragma unroll
    for (int g = 0; g < 4; g++) sum[g] = make_float2(0.f, 0.f);
#pragma unroll
    for (int s = 0; s < NSPLIT; s++) {
        size_t pb = (size_t)(s * 8 + q) * H4;
#pragma unroll
        for (int g = 0; g < 4; g++) {
            float2 p = gp[pb + g * 1024 + n];
            sum[g].x += p.x; sum[g].y += p.y;
        }
    }
    float bias[4];
#pragma unroll
    for (int g = 0; g < 4; g++) {
        int j = g * 1024 + n;
        bias[g] = Wib[j] + Whb[j];
    }

    const int b0 = 2 * q, b1 = 2 * q + 1;
    float pre0[4], pre1[4];
#pragma unroll
    for (int g = 0; g < 4; g++) {
        pre0[g] = sum[g].x + bias[g];
        pre1[g] = sum[g].y + bias[g];
    }

    {
        float ig = 1.0f / (1.0f + expf(-pre0[0]));
        float fg = 1.0f / (1.0f + expf(-pre0[1]));
        float gg = tanhf(pre0[2]);
        float og = 1.0f / (1.0f + expf(-pre0[3]));
        float cn = fg * c[b0 * 1024 + n] + ig * gg;
        out[b0 * 1024 + n] = og * tanhf(cn);
        out[Bb * 1024 + b0 * 1024 + n] = cn;
    }
    {
        float ig = 1.0f / (1.0f + expf(-pre1[0]));
        float fg = 1.0f / (1.0f + expf(-pre1[1]));
        float gg = tanhf(pre1[2]);
        float og = 1.0f / (1.0f + expf(-pre1[3]));
        float cn = fg * c[b1 * 1024 + n] + ig * gg;
        out[b1 * 1024 + n] = og * tanhf(cn);
        out[Bb * 1024 + b1 * 1024 + n] = cn;
    }
}

// ---------------------------------------------------------------------------
// Inputs (metadata order): x, h, c, context, Wi, Wi_b, Wh, Wh_b, AZ_il, AZ_ir,
// AZ_hl, AZ_hr.  context / AZ_* are dead (multiplied by 0 in the reference).
// ---------------------------------------------------------------------------
extern "C" void kernel_launch(void* const* d_in, const int* in_sizes, int n_in,
                              void* d_out, int out_size)
{
    (void)in_sizes; (void)n_in; (void)out_size;
    const float* x   = (const float*)d_in[0];
    const float* h   = (const float*)d_in[1];
    const float* c   = (const float*)d_in[2];
    const float* Wi  = (const float*)d_in[4];
    const float* Wib = (const float*)d_in[5];
    const float* Wh  = (const float*)d_in[6];
    const float* Whb = (const float*)d_in[7];
    float* out = (float*)d_out;

    static int configured = 0;
    if (!configured) {
        cudaFuncSetAttribute(gemm_part,
                             cudaFuncAttributeMaxDynamicSharedMemorySize,
                             SMEM_BYTES);
        configured = 1;
    }

    dim3 g1(8, NKC, 2);
    gemm_part<<<g1, TPB, SMEM_BYTES>>>(Wi, Wh, x, h);
    reduce_gates<<<8192 / 256, 256>>>(Wib, Whb, c, out);
}

// round 9
// speedup vs baseline: 1.0153x; 1.0153x over previous
#include <cuda_runtime.h>
#include <cstdint>

#define Bb   16
#define H4   4096
#define KC   128           // k-rows per block
#define NKC  8             // k-chunks (1024 / KC)
#define NSPLIT 16          // NKC * 2 matrices
#define TPB  512
#define SK   16            // k-rows per pipeline stage (32 KB)
#define NST  (KC / SK)     // 8 stages
#define RS   4             // ring slots
#define JT   512           // columns per j-tile (2KB rows)
#define ROW_BYTES  (JT * 4)
#define STAGE_BYTES (SK * ROW_BYTES)
#define SMEM_BYTES (RS * SK * JT * 4 + KC * Bb * 4 + RS * 8)

// scratch: 128 float2-planes of [H4]; plane p = sp*8 + q holds {b=2q, b=2q+1}
__device__ float g_part[(size_t)NSPLIT * Bb * H4];   // 4 MB

__device__ __forceinline__ unsigned long long pack2(float lo, float hi) {
    unsigned long long r;
    asm("mov.b64 %0, {%1, %2};" : "=l"(r) : "f"(lo), "f"(hi));
    return r;
}
__device__ __forceinline__ unsigned long long fma2(unsigned long long a,
                                                   unsigned long long b,
                                                   unsigned long long c) {
    unsigned long long d;
    asm("fma.rn.f32x2 %0, %1, %2, %3;" : "=l"(d) : "l"(a), "l"(b), "l"(c));
    return d;
}
__device__ __forceinline__ uint32_t smem_u32(const void* p) {
    uint32_t a;
    asm("{ .reg .u64 t; cvta.to.shared.u64 t, %1; cvt.u32.u64 %0, t; }"
        : "=r"(a) : "l"(p));
    return a;
}
__device__ __forceinline__ void mbar_init(uint32_t mbar, uint32_t cnt) {
    asm volatile("mbarrier.init.shared.b64 [%0], %1;" :: "r"(mbar), "r"(cnt) : "memory");
}
__device__ __forceinline__ void mbar_expect_tx(uint32_t mbar, uint32_t bytes) {
    asm volatile("mbarrier.arrive.expect_tx.shared.b64 _, [%0], %1;"
                 :: "r"(mbar), "r"(bytes) : "memory");
}
__device__ __forceinline__ void mbar_wait(uint32_t mbar, uint32_t phase) {
    asm volatile(
        "{\n\t.reg .pred P;\n\t"
        "W_%=:\n\t"
        "mbarrier.try_wait.parity.acquire.cta.shared::cta.b64 P, [%0], %1, 0x989680;\n\t"
        "@P bra D_%=;\n\t"
        "bra W_%=;\n\t"
        "D_%=:\n\t}"
        :: "r"(mbar), "r"(phase) : "memory");
}
__device__ __forceinline__ void bulk_copy(uint32_t dst_smem, const void* src,
                                          uint32_t bytes, uint32_t mbar) {
    asm volatile(
        "cp.async.bulk.shared::cluster.global.mbarrier::complete_tx::bytes "
        "[%0], [%1], %2, [%3];"
        :: "r"(dst_smem), "l"(src), "r"(bytes), "r"(mbar) : "memory");
}

// ---------------------------------------------------------------------------
// Kernel 1: split-K GEMM partials, deep TMA-engine weight pipeline.
// grid = (8 j-tiles, 8 k-chunks, 2 matrices) = 128 blocks (1 wave), 512 thr.
// Ring of 4 x 32KB smem stages issued ahead -> ~96-128KB in flight / block.
// Per thread: 1 col x 16 batches (8 f32x2 pairs); per k-row:
// 1 LDS.32 (w) + 4 broadcast LDS.128 (acts) + 8 FFMA2.
// ---------------------------------------------------------------------------
__global__ __launch_bounds__(TPB, 1) void gemm_part(
    const float* __restrict__ Wi, const float* __restrict__ Wh,
    const float* __restrict__ x,  const float* __restrict__ h)
{
    extern __shared__ char dsm[];
    float* wsm    = reinterpret_cast<float*>(dsm);            // RS*SK*JT floats
    float* sh_act = wsm + RS * SK * JT;                       // KC*Bb floats
    unsigned long long* mbar =
        reinterpret_cast<unsigned long long*>(sh_act + KC * Bb);

    const int jt  = blockIdx.x;            // 0..7
    const int kc  = blockIdx.y;            // 0..7
    const int mat = blockIdx.z;            // 0: Wi/x, 1: Wh/h
    const float* __restrict__ W   = mat ? Wh : Wi;
    const float* __restrict__ act = mat ? h  : x;
    const int k0  = kc * KC;
    const int tid = threadIdx.x;

    uint32_t mb[RS];
#pragma unroll
    for (int i = 0; i < RS; i++) mb[i] = smem_u32(&mbar[i]);
    const uint32_t wbase = smem_u32(wsm);
    const float* Wbase = W + (size_t)k0 * H4 + jt * JT;

    if (tid == 0) {
#pragma unroll
        for (int i = 0; i < RS; i++) mbar_init(mb[i], 1);
    }

    // stage activations: coalesced gmem read, smem scatter [k][b]
    for (int i = tid; i < Bb * KC; i += TPB) {
        int b = i >> 7;
        int k = i & (KC - 1);
        sh_act[k * Bb + b] = act[b * 1024 + k0 + k];
    }
    __syncthreads();

    // prologue: fill the whole ring (4 stages = 128 KB in flight)
    if (tid == 0) {
#pragma unroll
        for (int st = 0; st < RS; st++) {
            mbar_expect_tx(mb[st], STAGE_BYTES);
#pragma unroll
            for (int r = 0; r < SK; r++)
                bulk_copy(wbase + (st * SK + r) * ROW_BYTES,
                          Wbase + (size_t)(st * SK + r) * H4, ROW_BYTES, mb[st]);
        }
    }

    unsigned long long acc[8];             // batch-pairs for this column
#pragma unroll
    for (int q = 0; q < 8; q++) acc[q] = 0ull;

    for (int s = 0; s < NST; s++) {
        const int slot = s & (RS - 1);
        mbar_wait(mb[slot], (s >> 2) & 1);
        const float* wst = wsm + slot * SK * JT;

#pragma unroll
        for (int r = 0; r < SK; r++) {
            const int k = s * SK + r;
            float w = wst[r * JT + tid];
            const float* ak = &sh_act[k * Bb];
            ulonglong2 A0 = *reinterpret_cast<const ulonglong2*>(ak);
            ulonglong2 A1 = *reinterpret_cast<const ulonglong2*>(ak + 4);
            ulonglong2 A2 = *reinterpret_cast<const ulonglong2*>(ak + 8);
            ulonglong2 A3 = *reinterpret_cast<const ulonglong2*>(ak + 12);
            unsigned long long wv = pack2(w, w);
            acc[0] = fma2(wv, A0.x, acc[0]);
            acc[1] = fma2(wv, A0.y, acc[1]);
            acc[2] = fma2(wv, A1.x, acc[2]);
            acc[3] = fma2(wv, A1.y, acc[3]);
            acc[4] = fma2(wv, A2.x, acc[4]);
            acc[5] = fma2(wv, A2.y, acc[5]);
            acc[6] = fma2(wv, A3.x, acc[6]);
            acc[7] = fma2(wv, A3.y, acc[7]);
        }

        // barrier only needed before refilling this slot
        if (s + RS < NST) {
            __syncthreads();
            if (tid == 0) {
                mbar_expect_tx(mb[slot], STAGE_BYTES);
#pragma unroll
                for (int r = 0; r < SK; r++)
                    bulk_copy(wbase + (slot * SK + r) * ROW_BYTES,
                              Wbase + (size_t)((s + RS) * SK + r) * H4,
                              ROW_BYTES, mb[slot]);
            }
        }
    }

    // epilogue: coalesced STG.64 into per-(split, q) float2 planes
    const int sp = mat * NKC + kc;
    const int j0 = jt * JT + tid;
#pragma unroll
    for (int q = 0; q < 8; q++) {
        unsigned long long* plane =
            reinterpret_cast<unsigned long long*>(g_part) + (size_t)(sp * 8 + q) * H4;
        plane[j0] = acc[q];
    }
}

// ---------------------------------------------------------------------------
// Kernel 2 (fused): reduce 16 partials + biases + LSTM gates -> out.
// grid = 128 blocks x 256 threads; block = (q = bid&7, n-chunk = bid>>3).
// Phase 1: thread (g, nl) sums 16 splits of float2 + bias -> smem.
// Phase 2: 128 threads apply gates for batches 2q, 2q+1, 64 columns.
// out = [h_new (B*H) | c_new (B*H)]
// ---------------------------------------------------------------------------
__global__ __launch_bounds__(256) void reduce_gates(
    const float* __restrict__ Wib, const float* __restrict__ Whb,
    const float* __restrict__ c,   float* __restrict__ out)
{
    __shared__ float2 sg[4][64];

    const int bid = blockIdx.x;        // 0..127
    const int q   = bid & 7;
    const int nc  = bid >> 3;          // 0..15
    const int tid = threadIdx.x;
    const int g   = tid >> 6;          // gate 0..3
    const int nl  = tid & 63;
    const int n   = nc * 64 + nl;

    const float2* gp = reinterpret_cast<const float2*>(g_part);
    float2 s = make_float2(0.f, 0.f);
#pragma unroll
    for (int sp = 0; sp < NSPLIT; sp++) {
        float2 p = gp[(size_t)(sp * 8 + q) * H4 + g * 1024 + n];
        s.x += p.x; s.y += p.y;
    }
    float bias = Wib[g * 1024 + n] + Whb[g * 1024 + n];
    s.x += bias; s.y += bias;
    sg[g][nl] = s;
    __syncthreads();

    if (tid < 128) {
        const int bl  = tid >> 6;      // 0/1 within batch-pair
        const int nl2 = tid & 63;
        const int n2  = nc * 64 + nl2;
        const int b   = 2 * q + bl;
        float iv = bl ? sg[0][nl2].y : sg[0][nl2].x;
        float fv = bl ? sg[1][nl2].y : sg[1][nl2].x;
        float gv = bl ? sg[2][nl2].y : sg[2][nl2].x;
        float ov = bl ? sg[3][nl2].y : sg[3][nl2].x;
        float ig = 1.0f / (1.0f + expf(-iv));
        float fg = 1.0f / (1.0f + expf(-fv));
        float gg = tanhf(gv);
        float og = 1.0f / (1.0f + expf(-ov));
        float cn = fg * c[b * 1024 + n2] + ig * gg;
        out[b * 1024 + n2] = og * tanhf(cn);
        out[Bb * 1024 + b * 1024 + n2] = cn;
    }
}

// ---------------------------------------------------------------------------
// Inputs (metadata order): x, h, c, context, Wi, Wi_b, Wh, Wh_b, AZ_il, AZ_ir,
// AZ_hl, AZ_hr.  context / AZ_* are dead (multiplied by 0 in the reference).
// ---------------------------------------------------------------------------
extern "C" void kernel_launch(void* const* d_in, const int* in_sizes, int n_in,
                              void* d_out, int out_size)
{
    (void)in_sizes; (void)n_in; (void)out_size;
    const float* x   = (const float*)d_in[0];
    const float* h   = (const float*)d_in[1];
    const float* c   = (const float*)d_in[2];
    const float* Wi  = (const float*)d_in[4];
    const float* Wib = (const float*)d_in[5];
    const float* Wh  = (const float*)d_in[6];
    const float* Whb = (const float*)d_in[7];
    float* out = (float*)d_out;

    static int configured = 0;
    if (!configured) {
        cudaFuncSetAttribute(gemm_part,
                             cudaFuncAttributeMaxDynamicSharedMemorySize,
                             SMEM_BYTES);
        configured = 1;
    }

    dim3 g1(8, NKC, 2);
    gemm_part<<<g1, TPB, SMEM_BYTES>>>(Wi, Wh, x, h);
    reduce_gates<<<128, 256>>>(Wib, Whb, c, out);
}

// round 10
// speedup vs baseline: 1.1218x; 1.1049x over previous
#include <cuda_runtime.h>
#include <cstdint>

#define Bb    16
#define H4    4096
#define KC    32            // k-rows per block
#define NKC   32            // k-chunks per matrix (1024 / KC)
#define NSPLIT 64           // NKC * 2 matrices
#define TPB   256
#define COLS  2048          // columns per block (8 per thread)
#define SK    4             // k-rows per pipeline stage (32 KB)
#define NST   (KC / SK)     // 8 stages
#define RS    4             // ring slots
#define ROW_BYTES   (COLS * 4)          // 8 KB
#define STAGE_BYTES (SK * ROW_BYTES)    // 32 KB
#define SMEM_BYTES  (RS * SK * COLS * 4 + KC * Bb * 4 + RS * 8)

// scratch: 512 float2-planes of [H4]; plane p = sp*8 + q holds {b=2q, b=2q+1}
__device__ float g_part[(size_t)NSPLIT * Bb * H4];   // 16 MB

__device__ __forceinline__ unsigned long long pack2(float lo, float hi) {
    unsigned long long r;
    asm("mov.b64 %0, {%1, %2};" : "=l"(r) : "f"(lo), "f"(hi));
    return r;
}
__device__ __forceinline__ unsigned long long fma2(unsigned long long a,
                                                   unsigned long long b,
                                                   unsigned long long c) {
    unsigned long long d;
    asm("fma.rn.f32x2 %0, %1, %2, %3;" : "=l"(d) : "l"(a), "l"(b), "l"(c));
    return d;
}
__device__ __forceinline__ uint32_t smem_u32(const void* p) {
    uint32_t a;
    asm("{ .reg .u64 t; cvta.to.shared.u64 t, %1; cvt.u32.u64 %0, t; }"
        : "=r"(a) : "l"(p));
    return a;
}
__device__ __forceinline__ void mbar_init(uint32_t mbar, uint32_t cnt) {
    asm volatile("mbarrier.init.shared.b64 [%0], %1;" :: "r"(mbar), "r"(cnt) : "memory");
}
__device__ __forceinline__ void mbar_expect_tx(uint32_t mbar, uint32_t bytes) {
    asm volatile("mbarrier.arrive.expect_tx.shared.b64 _, [%0], %1;"
                 :: "r"(mbar), "r"(bytes) : "memory");
}
__device__ __forceinline__ void mbar_wait(uint32_t mbar, uint32_t phase) {
    asm volatile(
        "{\n\t.reg .pred P;\n\t"
        "W_%=:\n\t"
        "mbarrier.try_wait.parity.acquire.cta.shared::cta.b64 P, [%0], %1, 0x989680;\n\t"
        "@P bra D_%=;\n\t"
        "bra W_%=;\n\t"
        "D_%=:\n\t}"
        :: "r"(mbar), "r"(phase) : "memory");
}
__device__ __forceinline__ void bulk_copy(uint32_t dst_smem, const void* src,
                                          uint32_t bytes, uint32_t mbar) {
    asm volatile(
        "cp.async.bulk.shared::cluster.global.mbarrier::complete_tx::bytes "
        "[%0], [%1], %2, [%3];"
        :: "r"(dst_smem), "l"(src), "r"(bytes), "r"(mbar) : "memory");
}

// ---------------------------------------------------------------------------
// Kernel 1: split-K GEMM partials.
// grid = (2 j-tiles, 32 k-chunks, 2 matrices) = 128 blocks, 256 threads.
// Ring: 4 x 32KB TMA stages (128KB smem in flight per block).
// Per thread: 8 cols x 16 batches = 64 f32x2 accumulators; per k-row:
// 2 LDS.128 (weights) + 4 broadcast LDS.128 (acts) + 64 FFMA2.
// ---------------------------------------------------------------------------
__global__ __launch_bounds__(TPB, 1) void gemm_part(
    const float* __restrict__ Wi, const float* __restrict__ Wh,
    const float* __restrict__ x,  const float* __restrict__ h)
{
    extern __shared__ char dsm[];
    float* wsm    = reinterpret_cast<float*>(dsm);            // RS*SK*COLS
    float* sh_act = wsm + RS * SK * COLS;                     // KC*Bb
    unsigned long long* mbar =
        reinterpret_cast<unsigned long long*>(sh_act + KC * Bb);

    const int jt  = blockIdx.x;            // 0..1
    const int kc  = blockIdx.y;            // 0..31
    const int mat = blockIdx.z;            // 0: Wi/x, 1: Wh/h
    const float* __restrict__ W   = mat ? Wh : Wi;
    const float* __restrict__ act = mat ? h  : x;
    const int k0  = kc * KC;
    const int tid = threadIdx.x;

    uint32_t mb[RS];
#pragma unroll
    for (int i = 0; i < RS; i++) mb[i] = smem_u32(&mbar[i]);
    const uint32_t wbase = smem_u32(wsm);
    const float* Wbase = W + (size_t)k0 * H4 + jt * COLS;

    if (tid == 0) {
#pragma unroll
        for (int i = 0; i < RS; i++) mbar_init(mb[i], 1);
    }

    // stage activations [k][b]
    for (int i = tid; i < Bb * KC; i += TPB) {
        int b = i >> 5;
        int k = i & (KC - 1);
        sh_act[k * Bb + b] = act[b * 1024 + k0 + k];
    }
    __syncthreads();

    // prologue: fill the whole ring (4 x 32KB in flight)
    if (tid == 0) {
#pragma unroll
        for (int st = 0; st < RS; st++) {
            mbar_expect_tx(mb[st], STAGE_BYTES);
#pragma unroll
            for (int r = 0; r < SK; r++)
                bulk_copy(wbase + (st * SK + r) * COLS * 4,
                          Wbase + (size_t)(st * SK + r) * H4, ROW_BYTES, mb[st]);
        }
    }

    unsigned long long acc[8][8];          // [col][batch-pair]
#pragma unroll
    for (int c = 0; c < 8; c++)
#pragma unroll
        for (int q = 0; q < 8; q++) acc[c][q] = 0ull;

    for (int s = 0; s < NST; s++) {
        const int slot = s & (RS - 1);
        mbar_wait(mb[slot], (s >> 2) & 1);
        const float* wst = wsm + slot * SK * COLS;

#pragma unroll
        for (int r = 0; r < SK; r++) {
            const int k = s * SK + r;
            const float* wp = &wst[r * COLS + tid * 8];
            float4 wA = *reinterpret_cast<const float4*>(wp);
            float4 wB = *reinterpret_cast<const float4*>(wp + 4);
            const float* ak = &sh_act[k * Bb];
            ulonglong2 A0 = *reinterpret_cast<const ulonglong2*>(ak);
            ulonglong2 A1 = *reinterpret_cast<const ulonglong2*>(ak + 4);
            ulonglong2 A2 = *reinterpret_cast<const ulonglong2*>(ak + 8);
            ulonglong2 A3 = *reinterpret_cast<const ulonglong2*>(ak + 12);
            unsigned long long wv[8];
            wv[0] = pack2(wA.x, wA.x);  wv[1] = pack2(wA.y, wA.y);
            wv[2] = pack2(wA.z, wA.z);  wv[3] = pack2(wA.w, wA.w);
            wv[4] = pack2(wB.x, wB.x);  wv[5] = pack2(wB.y, wB.y);
            wv[6] = pack2(wB.z, wB.z);  wv[7] = pack2(wB.w, wB.w);
#pragma unroll
            for (int c = 0; c < 8; c++) {
                acc[c][0] = fma2(wv[c], A0.x, acc[c][0]);
                acc[c][1] = fma2(wv[c], A0.y, acc[c][1]);
                acc[c][2] = fma2(wv[c], A1.x, acc[c][2]);
                acc[c][3] = fma2(wv[c], A1.y, acc[c][3]);
                acc[c][4] = fma2(wv[c], A2.x, acc[c][4]);
                acc[c][5] = fma2(wv[c], A2.y, acc[c][5]);
                acc[c][6] = fma2(wv[c], A3.x, acc[c][6]);
                acc[c][7] = fma2(wv[c], A3.y, acc[c][7]);
            }
        }

        // refill this slot with stage s+RS
        if (s + RS < NST) {
            __syncthreads();
            if (tid == 0) {
                mbar_expect_tx(mb[slot], STAGE_BYTES);
#pragma unroll
                for (int r = 0; r < SK; r++)
                    bulk_copy(wbase + (slot * SK + r) * COLS * 4,
                              Wbase + (size_t)((s + RS) * SK + r) * H4,
                              ROW_BYTES, mb[slot]);
            }
        }
    }

    // epilogue: STG.128 into per-(split, q) float2 planes
    const int sp = mat * NKC + kc;         // 0..63
    const int j0 = jt * COLS + tid * 8;
#pragma unroll
    for (int q = 0; q < 8; q++) {
        float2* plane = reinterpret_cast<float2*>(g_part) + (size_t)(sp * 8 + q) * H4;
#pragma unroll
        for (int cp = 0; cp < 4; cp++)
            *reinterpret_cast<ulonglong2*>(plane + j0 + cp * 2) =
                make_ulonglong2(acc[cp * 2][q], acc[cp * 2 + 1][q]);
    }
}

// ---------------------------------------------------------------------------
// Kernel 2 (fused): reduce 64 partials + biases + LSTM gates -> out.
// grid = 128 blocks x 256 threads; block = (q = bid&7, n-chunk = bid>>3).
// Phase 1: thread (g, nl) sums 64 splits (two register-batched passes of 32)
// + bias -> smem.  Phase 2: 128 threads apply gates for batches 2q, 2q+1.
// out = [h_new (B*H) | c_new (B*H)]
// ---------------------------------------------------------------------------
__global__ __launch_bounds__(256, 1) void reduce_gates(
    const float* __restrict__ Wib, const float* __restrict__ Whb,
    const float* __restrict__ c,   float* __restrict__ out)
{
    __shared__ float2 sg[4][64];

    const int bid = blockIdx.x;        // 0..127
    const int q   = bid & 7;
    const int nc  = bid >> 3;          // 0..15
    const int tid = threadIdx.x;
    const int g   = tid >> 6;          // gate 0..3
    const int nl  = tid & 63;
    const int n   = nc * 64 + nl;

    const float2* gp = reinterpret_cast<const float2*>(g_part)
                     + (size_t)q * H4 + g * 1024 + n;
    float sx = 0.f, sy = 0.f;
#pragma unroll
    for (int half = 0; half < 2; half++) {
        float2 t[32];
#pragma unroll
        for (int i = 0; i < 32; i++)
            t[i] = gp[(size_t)((half * 32 + i) * 8) * H4];
#pragma unroll
        for (int i = 0; i < 32; i++) { sx += t[i].x; sy += t[i].y; }
    }
    float bias = Wib[g * 1024 + n] + Whb[g * 1024 + n];
    sg[g][nl] = make_float2(sx + bias, sy + bias);
    __syncthreads();

    if (tid < 128) {
        const int bl  = tid >> 6;      // 0/1 within batch-pair
        const int nl2 = tid & 63;
        const int n2  = nc * 64 + nl2;
        const int b   = 2 * q + bl;
        float iv = bl ? sg[0][nl2].y : sg[0][nl2].x;
        float fv = bl ? sg[1][nl2].y : sg[1][nl2].x;
        float gv = bl ? sg[2][nl2].y : sg[2][nl2].x;
        float ov = bl ? sg[3][nl2].y : sg[3][nl2].x;
        float ig = 1.0f / (1.0f + expf(-iv));
        float fg = 1.0f / (1.0f + expf(-fv));
        float gg = tanhf(gv);
        float og = 1.0f / (1.0f + expf(-ov));
        float cn = fg * c[b * 1024 + n2] + ig * gg;
        out[b * 1024 + n2] = og * tanhf(cn);
        out[Bb * 1024 + b * 1024 + n2] = cn;
    }
}

// ---------------------------------------------------------------------------
// Inputs (metadata order): x, h, c, context, Wi, Wi_b, Wh, Wh_b, AZ_il, AZ_ir,
// AZ_hl, AZ_hr.  context / AZ_* are dead (multiplied by 0 in the reference).
// ---------------------------------------------------------------------------
extern "C" void kernel_launch(void* const* d_in, const int* in_sizes, int n_in,
                              void* d_out, int out_size)
{
    (void)in_sizes; (void)n_in; (void)out_size;
    const float* x   = (const float*)d_in[0];
    const float* h   = (const float*)d_in[1];
    const float* c   = (const float*)d_in[2];
    const float* Wi  = (const float*)d_in[4];
    const float* Wib = (const float*)d_in[5];
    const float* Wh  = (const float*)d_in[6];
    const float* Whb = (const float*)d_in[7];
    float* out = (float*)d_out;

    cudaFuncSetAttribute(gemm_part,
                         cudaFuncAttributeMaxDynamicSharedMemorySize,
                         SMEM_BYTES);

    dim3 g1(2, NKC, 2);
    gemm_part<<<g1, TPB, SMEM_BYTES>>>(Wi, Wh, x, h);
    reduce_gates<<<128, 256>>>(Wib, Whb, c, out);
}

// round 11
// speedup vs baseline: 1.2416x; 1.1067x over previous
#include <cuda_runtime.h>
#include <cstdint>

#define Bb    16
#define H4    4096
#define KC    64            // k-rows per block
#define NKC   16            // k-chunks per matrix
#define NSPLIT 32           // NKC * 2 matrices
#define TPB   256
#define COLS  1024          // columns per block (4 per thread)
#define SK    4             // k-rows per stage (16 KB)
#define NST   (KC / SK)     // 16 stages
#define RS    8             // ring slots (128 KB)
#define ROW_BYTES   (COLS * 4)          // 4 KB
#define STAGE_BYTES (SK * ROW_BYTES)    // 16 KB
#define SMEM_BYTES  (RS * SK * COLS * 4 + KC * Bb * 4 + RS * 8)

// scratch: 256 float2-planes of [H4]; plane p = sp*8 + q holds {b=2q, b=2q+1}
__device__ float g_part[(size_t)NSPLIT * Bb * H4];   // 8 MB

__device__ __forceinline__ unsigned long long pack2(float lo, float hi) {
    unsigned long long r;
    asm("mov.b64 %0, {%1, %2};" : "=l"(r) : "f"(lo), "f"(hi));
    return r;
}
__device__ __forceinline__ unsigned long long fma2(unsigned long long a,
                                                   unsigned long long b,
                                                   unsigned long long c) {
    unsigned long long d;
    asm("fma.rn.f32x2 %0, %1, %2, %3;" : "=l"(d) : "l"(a), "l"(b), "l"(c));
    return d;
}
__device__ __forceinline__ uint32_t smem_u32(const void* p) {
    uint32_t a;
    asm("{ .reg .u64 t; cvta.to.shared.u64 t, %1; cvt.u32.u64 %0, t; }"
        : "=r"(a) : "l"(p));
    return a;
}
__device__ __forceinline__ void mbar_init(uint32_t mbar, uint32_t cnt) {
    asm volatile("mbarrier.init.shared.b64 [%0], %1;" :: "r"(mbar), "r"(cnt) : "memory");
}
__device__ __forceinline__ void mbar_expect_tx(uint32_t mbar, uint32_t bytes) {
    asm volatile("mbarrier.arrive.expect_tx.shared.b64 _, [%0], %1;"
                 :: "r"(mbar), "r"(bytes) : "memory");
}
__device__ __forceinline__ void mbar_wait(uint32_t mbar, uint32_t phase) {
    asm volatile(
        "{\n\t.reg .pred P;\n\t"
        "W_%=:\n\t"
        "mbarrier.try_wait.parity.acquire.cta.shared::cta.b64 P, [%0], %1, 0x989680;\n\t"
        "@P bra D_%=;\n\t"
        "bra W_%=;\n\t"
        "D_%=:\n\t}"
        :: "r"(mbar), "r"(phase) : "memory");
}
__device__ __forceinline__ void bulk_copy(uint32_t dst_smem, const void* src,
                                          uint32_t bytes, uint32_t mbar) {
    asm volatile(
        "cp.async.bulk.shared::cluster.global.mbarrier::complete_tx::bytes "
        "[%0], [%1], %2, [%3];"
        :: "r"(dst_smem), "l"(src), "r"(bytes), "r"(mbar) : "memory");
}

// ---------------------------------------------------------------------------
// Kernel 1: split-K GEMM partials.
// grid = (4 j-tiles, 16 k-chunks, 2 matrices) = 128 blocks, 256 threads.
// Ring: 8 x 16KB TMA stages (128KB smem in flight per block).
// Per thread: 4 cols x 16 batches = 32 f32x2 accumulators; per k-row:
// 1 LDS.128 (weights) + 4 broadcast LDS.128 (acts) + 32 FFMA2.
// ---------------------------------------------------------------------------
__global__ __launch_bounds__(TPB, 1) void gemm_part(
    const float* __restrict__ Wi, const float* __restrict__ Wh,
    const float* __restrict__ x,  const float* __restrict__ h)
{
    extern __shared__ char dsm[];
    float* wsm    = reinterpret_cast<float*>(dsm);            // RS*SK*COLS
    float* sh_act = wsm + RS * SK * COLS;                     // KC*Bb
    unsigned long long* mbar =
        reinterpret_cast<unsigned long long*>(sh_act + KC * Bb);

    const int jt  = blockIdx.x;            // 0..3
    const int kc  = blockIdx.y;            // 0..15
    const int mat = blockIdx.z;            // 0: Wi/x, 1: Wh/h
    const float* __restrict__ W   = mat ? Wh : Wi;
    const float* __restrict__ act = mat ? h  : x;
    const int k0  = kc * KC;
    const int tid = threadIdx.x;

    uint32_t mb[RS];
#pragma unroll
    for (int i = 0; i < RS; i++) mb[i] = smem_u32(&mbar[i]);
    const uint32_t wbase = smem_u32(wsm);
    const float* Wbase = W + (size_t)k0 * H4 + jt * COLS;

    if (tid == 0) {
#pragma unroll
        for (int i = 0; i < RS; i++) mbar_init(mb[i], 1);
    }

    // stage activations [k][b]
    for (int i = tid; i < Bb * KC; i += TPB) {
        int b = i >> 6;
        int k = i & (KC - 1);
        sh_act[k * Bb + b] = act[b * 1024 + k0 + k];
    }
    __syncthreads();   // orders mbar_init before any wait; acts visible

    // prologue: fill the whole ring (8 x 16KB = 128 KB in flight)
    if (tid == 0) {
#pragma unroll
        for (int st = 0; st < RS; st++) {
            mbar_expect_tx(mb[st], STAGE_BYTES);
#pragma unroll
            for (int r = 0; r < SK; r++)
                bulk_copy(wbase + (st * SK + r) * ROW_BYTES,
                          Wbase + (size_t)(st * SK + r) * H4, ROW_BYTES, mb[st]);
        }
    }

    unsigned long long acc[4][8];          // [col][batch-pair]
#pragma unroll
    for (int c = 0; c < 4; c++)
#pragma unroll
        for (int q = 0; q < 8; q++) acc[c][q] = 0ull;

    for (int s = 0; s < NST; s++) {
        const int slot = s & (RS - 1);
        mbar_wait(mb[slot], (s >> 3) & 1);
        const float* wst = wsm + slot * SK * COLS;

#pragma unroll
        for (int r = 0; r < SK; r++) {
            const int k = s * SK + r;
            float4 w = *reinterpret_cast<const float4*>(&wst[r * COLS + tid * 4]);
            const float* ak = &sh_act[k * Bb];
            ulonglong2 A0 = *reinterpret_cast<const ulonglong2*>(ak);
            ulonglong2 A1 = *reinterpret_cast<const ulonglong2*>(ak + 4);
            ulonglong2 A2 = *reinterpret_cast<const ulonglong2*>(ak + 8);
            ulonglong2 A3 = *reinterpret_cast<const ulonglong2*>(ak + 12);
            unsigned long long wv[4];
            wv[0] = pack2(w.x, w.x);  wv[1] = pack2(w.y, w.y);
            wv[2] = pack2(w.z, w.z);  wv[3] = pack2(w.w, w.w);
#pragma unroll
            for (int c = 0; c < 4; c++) {
                acc[c][0] = fma2(wv[c], A0.x, acc[c][0]);
                acc[c][1] = fma2(wv[c], A0.y, acc[c][1]);
                acc[c][2] = fma2(wv[c], A1.x, acc[c][2]);
                acc[c][3] = fma2(wv[c], A1.y, acc[c][3]);
                acc[c][4] = fma2(wv[c], A2.x, acc[c][4]);
                acc[c][5] = fma2(wv[c], A2.y, acc[c][5]);
                acc[c][6] = fma2(wv[c], A3.x, acc[c][6]);
                acc[c][7] = fma2(wv[c], A3.y, acc[c][7]);
            }
        }

        // refill this slot with stage s+RS (only first 8 stages refill)
        if (s + RS < NST) {
            __syncthreads();
            if (tid == 0) {
                mbar_expect_tx(mb[slot], STAGE_BYTES);
#pragma unroll
                for (int r = 0; r < SK; r++)
                    bulk_copy(wbase + (slot * SK + r) * ROW_BYTES,
                              Wbase + (size_t)((s + RS) * SK + r) * H4,
                              ROW_BYTES, mb[slot]);
            }
        }
    }

    // epilogue: STG.128 into per-(split, q) float2 planes
    const int sp = mat * NKC + kc;         // 0..31
    const int j0 = jt * COLS + tid * 4;
#pragma unroll
    for (int q = 0; q < 8; q++) {
        float2* plane = reinterpret_cast<float2*>(g_part) + (size_t)(sp * 8 + q) * H4;
        *reinterpret_cast<ulonglong2*>(plane + j0) =
            make_ulonglong2(acc[0][q], acc[1][q]);
        *reinterpret_cast<ulonglong2*>(plane + j0 + 2) =
            make_ulonglong2(acc[2][q], acc[3][q]);
    }
}

// ---------------------------------------------------------------------------
// Kernel 2 (fused): reduce 32 partials + biases + LSTM gates -> out.
// grid = 64 blocks x 512 threads; block = (q = bid&7, nc = bid>>3).
// Phase 1: thread (g, nl) sums 32 splits (register-batched) + bias -> smem.
// Phase 2: 256 threads apply gates for batches 2q, 2q+1 over 128 columns.
// out = [h_new (B*H) | c_new (B*H)]
// ---------------------------------------------------------------------------
__global__ __launch_bounds__(512, 1) void reduce_gates(
    const float* __restrict__ Wib, const float* __restrict__ Whb,
    const float* __restrict__ c,   float* __restrict__ out)
{
    __shared__ float2 sg[4][128];

    const int bid = blockIdx.x;        // 0..63
    const int q   = bid & 7;
    const int nc  = bid >> 3;          // 0..7
    const int tid = threadIdx.x;
    const int g   = tid >> 7;          // gate 0..3
    const int nl  = tid & 127;
    const int n   = nc * 128 + nl;

    const float2* gp = reinterpret_cast<const float2*>(g_part)
                     + (size_t)q * H4 + g * 1024 + n;
    float2 t[NSPLIT];
#pragma unroll
    for (int i = 0; i < NSPLIT; i++)
        t[i] = gp[(size_t)(i * 8) * H4];
    float sx = 0.f, sy = 0.f;
#pragma unroll
    for (int i = 0; i < NSPLIT; i++) { sx += t[i].x; sy += t[i].y; }

    float bias = Wib[g * 1024 + n] + Whb[g * 1024 + n];
    sg[g][nl] = make_float2(sx + bias, sy + bias);
    __syncthreads();

    if (tid < 256) {
        const int bl  = tid >> 7;      // 0/1 within batch-pair
        const int nl2 = tid & 127;
        const int n2  = nc * 128 + nl2;
        const int b   = 2 * q + bl;
        float iv = bl ? sg[0][nl2].y : sg[0][nl2].x;
        float fv = bl ? sg[1][nl2].y : sg[1][nl2].x;
        float gv = bl ? sg[2][nl2].y : sg[2][nl2].x;
        float ov = bl ? sg[3][nl2].y : sg[3][nl2].x;
        float ig = 1.0f / (1.0f + expf(-iv));
        float fg = 1.0f / (1.0f + expf(-fv));
        float gg = tanhf(gv);
        float og = 1.0f / (1.0f + expf(-ov));
        float cn = fg * c[b * 1024 + n2] + ig * gg;
        out[b * 1024 + n2] = og * tanhf(cn);
        out[Bb * 1024 + b * 1024 + n2] = cn;
    }
}

// ---------------------------------------------------------------------------
// Inputs (metadata order): x, h, c, context, Wi, Wi_b, Wh, Wh_b, AZ_il, AZ_ir,
// AZ_hl, AZ_hr.  context / AZ_* are dead (multiplied by 0 in the reference).
// ---------------------------------------------------------------------------
extern "C" void kernel_launch(void* const* d_in, const int* in_sizes, int n_in,
                              void* d_out, int out_size)
{
    (void)in_sizes; (void)n_in; (void)out_size;
    const float* x   = (const float*)d_in[0];
    const float* h   = (const float*)d_in[1];
    const float* c   = (const float*)d_in[2];
    const float* Wi  = (const float*)d_in[4];
    const float* Wib = (const float*)d_in[5];
    const float* Wh  = (const float*)d_in[6];
    const float* Whb = (const float*)d_in[7];
    float* out = (float*)d_out;

    cudaFuncSetAttribute(gemm_part,
                         cudaFuncAttributeMaxDynamicSharedMemorySize,
                         SMEM_BYTES);

    dim3 g1(4, NKC, 2);
    gemm_part<<<g1, TPB, SMEM_BYTES>>>(Wi, Wh, x, h);
    reduce_gates<<<64, 512>>>(Wib, Whb, c, out);
}

// round 12
// speedup vs baseline: 1.2605x; 1.0152x over previous
#include <cuda_runtime.h>
#include <cstdint>

#define Bb    16
#define H4    4096
#define KC    64            // k-rows per block
#define NKC   16            // k-chunks per matrix
#define NSPLIT 32           // NKC * 2 matrices
#define TPB   256
#define COLS  1024          // columns per block (4 per thread)
#define SK    4             // k-rows per stage (16 KB)
#define NST   (KC / SK)     // 16 stages
#define RS    8             // ring slots (128 KB)
#define ROW_BYTES   (COLS * 4)          // 4 KB
#define STAGE_BYTES (SK * ROW_BYTES)    // 16 KB
#define SMEM_BYTES  (RS * SK * COLS * 4 + KC * Bb * 4 + RS * 8)

// scratch: 256 float2-planes of [H4]; plane p = sp*8 + q holds {b=2q, b=2q+1}
__device__ float g_part[(size_t)NSPLIT * Bb * H4];   // 8 MB

__device__ __forceinline__ unsigned long long pack2(float lo, float hi) {
    unsigned long long r;
    asm("mov.b64 %0, {%1, %2};" : "=l"(r) : "f"(lo), "f"(hi));
    return r;
}
__device__ __forceinline__ unsigned long long fma2(unsigned long long a,
                                                   unsigned long long b,
                                                   unsigned long long c) {
    unsigned long long d;
    asm("fma.rn.f32x2 %0, %1, %2, %3;" : "=l"(d) : "l"(a), "l"(b), "l"(c));
    return d;
}
__device__ __forceinline__ uint32_t smem_u32(const void* p) {
    uint32_t a;
    asm("{ .reg .u64 t; cvta.to.shared.u64 t, %1; cvt.u32.u64 %0, t; }"
        : "=r"(a) : "l"(p));
    return a;
}
__device__ __forceinline__ void mbar_init(uint32_t mbar, uint32_t cnt) {
    asm volatile("mbarrier.init.shared.b64 [%0], %1;" :: "r"(mbar), "r"(cnt) : "memory");
}
__device__ __forceinline__ void mbar_expect_tx(uint32_t mbar, uint32_t bytes) {
    asm volatile("mbarrier.arrive.expect_tx.shared.b64 _, [%0], %1;"
                 :: "r"(mbar), "r"(bytes) : "memory");
}
__device__ __forceinline__ void mbar_wait(uint32_t mbar, uint32_t phase) {
    asm volatile(
        "{\n\t.reg .pred P;\n\t"
        "W_%=:\n\t"
        "mbarrier.try_wait.parity.acquire.cta.shared::cta.b64 P, [%0], %1, 0x989680;\n\t"
        "@P bra D_%=;\n\t"
        "bra W_%=;\n\t"
        "D_%=:\n\t}"
        :: "r"(mbar), "r"(phase) : "memory");
}
__device__ __forceinline__ void bulk_copy(uint32_t dst_smem, const void* src,
                                          uint32_t bytes, uint32_t mbar) {
    asm volatile(
        "cp.async.bulk.shared::cluster.global.mbarrier::complete_tx::bytes "
        "[%0], [%1], %2, [%3];"
        :: "r"(dst_smem), "l"(src), "r"(bytes), "r"(mbar) : "memory");
}

// ---------------------------------------------------------------------------
// Kernel 1: split-K GEMM partials.
// grid = (4 j-tiles, 16 k-chunks, 2 matrices) = 128 blocks, 256 threads.
// Ring: 8 x 16KB TMA stages (128KB smem in flight per block).
// Per thread: 4 cols x 16 batches = 32 f32x2 accumulators; per k-row:
// 1 LDS.128 (weights) + 4 broadcast LDS.128 (acts) + 32 FFMA2.
// ---------------------------------------------------------------------------
__global__ __launch_bounds__(TPB, 1) void gemm_part(
    const float* __restrict__ Wi, const float* __restrict__ Wh,
    const float* __restrict__ x,  const float* __restrict__ h)
{
    extern __shared__ char dsm[];
    float* wsm    = reinterpret_cast<float*>(dsm);            // RS*SK*COLS
    float* sh_act = wsm + RS * SK * COLS;                     // KC*Bb
    unsigned long long* mbar =
        reinterpret_cast<unsigned long long*>(sh_act + KC * Bb);

    const int jt  = blockIdx.x;            // 0..3
    const int kc  = blockIdx.y;            // 0..15
    const int mat = blockIdx.z;            // 0: Wi/x, 1: Wh/h
    const float* __restrict__ W   = mat ? Wh : Wi;
    const float* __restrict__ act = mat ? h  : x;
    const int k0  = kc * KC;
    const int tid = threadIdx.x;

    uint32_t mb[RS];
#pragma unroll
    for (int i = 0; i < RS; i++) mb[i] = smem_u32(&mbar[i]);
    const uint32_t wbase = smem_u32(wsm);
    const float* Wbase = W + (size_t)k0 * H4 + jt * COLS;

    if (tid == 0) {
#pragma unroll
        for (int i = 0; i < RS; i++) mbar_init(mb[i], 1);
    }

    // stage activations [k][b]
    for (int i = tid; i < Bb * KC; i += TPB) {
        int b = i >> 6;
        int k = i & (KC - 1);
        sh_act[k * Bb + b] = act[b * 1024 + k0 + k];
    }
    __syncthreads();   // orders mbar_init before any wait; acts visible

    // prologue: fill the whole ring (8 x 16KB = 128 KB in flight)
    if (tid == 0) {
#pragma unroll
        for (int st = 0; st < RS; st++) {
            mbar_expect_tx(mb[st], STAGE_BYTES);
#pragma unroll
            for (int r = 0; r < SK; r++)
                bulk_copy(wbase + (st * SK + r) * ROW_BYTES,
                          Wbase + (size_t)(st * SK + r) * H4, ROW_BYTES, mb[st]);
        }
    }

    unsigned long long acc[4][8];          // [col][batch-pair]
#pragma unroll
    for (int c = 0; c < 4; c++)
#pragma unroll
        for (int q = 0; q < 8; q++) acc[c][q] = 0ull;

    for (int s = 0; s < NST; s++) {
        const int slot = s & (RS - 1);
        mbar_wait(mb[slot], (s >> 3) & 1);
        const float* wst = wsm + slot * SK * COLS;

#pragma unroll
        for (int r = 0; r < SK; r++) {
            const int k = s * SK + r;
            float4 w = *reinterpret_cast<const float4*>(&wst[r * COLS + tid * 4]);
            const float* ak = &sh_act[k * Bb];
            ulonglong2 A0 = *reinterpret_cast<const ulonglong2*>(ak);
            ulonglong2 A1 = *reinterpret_cast<const ulonglong2*>(ak + 4);
            ulonglong2 A2 = *reinterpret_cast<const ulonglong2*>(ak + 8);
            ulonglong2 A3 = *reinterpret_cast<const ulonglong2*>(ak + 12);
            unsigned long long wv[4];
            wv[0] = pack2(w.x, w.x);  wv[1] = pack2(w.y, w.y);
            wv[2] = pack2(w.z, w.z);  wv[3] = pack2(w.w, w.w);
#pragma unroll
            for (int c = 0; c < 4; c++) {
                acc[c][0] = fma2(wv[c], A0.x, acc[c][0]);
                acc[c][1] = fma2(wv[c], A0.y, acc[c][1]);
                acc[c][2] = fma2(wv[c], A1.x, acc[c][2]);
                acc[c][3] = fma2(wv[c], A1.y, acc[c][3]);
                acc[c][4] = fma2(wv[c], A2.x, acc[c][4]);
                acc[c][5] = fma2(wv[c], A2.y, acc[c][5]);
                acc[c][6] = fma2(wv[c], A3.x, acc[c][6]);
                acc[c][7] = fma2(wv[c], A3.y, acc[c][7]);
            }
        }

        // refill this slot with stage s+RS (only first 8 stages refill)
        if (s + RS < NST) {
            __syncthreads();
            if (tid == 0) {
                mbar_expect_tx(mb[slot], STAGE_BYTES);
#pragma unroll
                for (int r = 0; r < SK; r++)
                    bulk_copy(wbase + (slot * SK + r) * ROW_BYTES,
                              Wbase + (size_t)((s + RS) * SK + r) * H4,
                              ROW_BYTES, mb[slot]);
            }
        }
    }

    // epilogue: STG.128 into per-(split, q) float2 planes
    const int sp = mat * NKC + kc;         // 0..31
    const int j0 = jt * COLS + tid * 4;
#pragma unroll
    for (int q = 0; q < 8; q++) {
        float2* plane = reinterpret_cast<float2*>(g_part) + (size_t)(sp * 8 + q) * H4;
        *reinterpret_cast<ulonglong2*>(plane + j0) =
            make_ulonglong2(acc[0][q], acc[1][q]);
        *reinterpret_cast<ulonglong2*>(plane + j0 + 2) =
            make_ulonglong2(acc[2][q], acc[3][q]);
    }
}

// ---------------------------------------------------------------------------
// Kernel 2 (fused): reduce 32 partials + biases + LSTM gates -> out.
// grid = 64 blocks x 512 threads; block = (q = bid&7, nc = bid>>3).
// Phase 1: thread (g, nl) sums 32 splits (register-batched) + bias -> smem.
// Phase 2: 256 threads apply gates for batches 2q, 2q+1 over 128 columns.
// out = [h_new (B*H) | c_new (B*H)]
// ---------------------------------------------------------------------------
__global__ __launch_bounds__(512, 1) void reduce_gates(
    const float* __restrict__ Wib, const float* __restrict__ Whb,
    const float* __restrict__ c,   float* __restrict__ out)
{
    __shared__ float2 sg[4][128];

    const int bid = blockIdx.x;        // 0..63
    const int q   = bid & 7;
    const int nc  = bid >> 3;          // 0..7
    const int tid = threadIdx.x;
    const int g   = tid >> 7;          // gate 0..3
    const int nl  = tid & 127;
    const int n   = nc * 128 + nl;

    const float2* gp = reinterpret_cast<const float2*>(g_part)
                     + (size_t)q * H4 + g * 1024 + n;
    float2 t[NSPLIT];
#pragma unroll
    for (int i = 0; i < NSPLIT; i++)
        t[i] = gp[(size_t)(i * 8) * H4];
    float sx = 0.f, sy = 0.f;
#pragma unroll
    for (int i = 0; i < NSPLIT; i++) { sx += t[i].x; sy += t[i].y; }

    float bias = Wib[g * 1024 + n] + Whb[g * 1024 + n];
    sg[g][nl] = make_float2(sx + bias, sy + bias);
    __syncthreads();

    if (tid < 256) {
        const int bl  = tid >> 7;      // 0/1 within batch-pair
        const int nl2 = tid & 127;
        const int n2  = nc * 128 + nl2;
        const int b   = 2 * q + bl;
        float iv = bl ? sg[0][nl2].y : sg[0][nl2].x;
        float fv = bl ? sg[1][nl2].y : sg[1][nl2].x;
        float gv = bl ? sg[2][nl2].y : sg[2][nl2].x;
        float ov = bl ? sg[3][nl2].y : sg[3][nl2].x;
        float ig = 1.0f / (1.0f + expf(-iv));
        float fg = 1.0f / (1.0f + expf(-fv));
        float gg = tanhf(gv);
        float og = 1.0f / (1.0f + expf(-ov));
        float cn = fg * c[b * 1024 + n2] + ig * gg;
        out[b * 1024 + n2] = og * tanhf(cn);
        out[Bb * 1024 + b * 1024 + n2] = cn;
    }
}

// ---------------------------------------------------------------------------
// Inputs (metadata order): x, h, c, context, Wi, Wi_b, Wh, Wh_b, AZ_il, AZ_ir,
// AZ_hl, AZ_hr.  context / AZ_* are dead (multiplied by 0 in the reference).
// ---------------------------------------------------------------------------
extern "C" void kernel_launch(void* const* d_in, const int* in_sizes, int n_in,
                              void* d_out, int out_size)
{
    (void)in_sizes; (void)n_in; (void)out_size;
    const float* x   = (const float*)d_in[0];
    const float* h   = (const float*)d_in[1];
    const float* c   = (const float*)d_in[2];
    const float* Wi  = (const float*)d_in[4];
    const float* Wib = (const float*)d_in[5];
    const float* Wh  = (const float*)d_in[6];
    const float* Whb = (const float*)d_in[7];
    float* out = (float*)d_out;

    cudaFuncSetAttribute(gemm_part,
                         cudaFuncAttributeMaxDynamicSharedMemorySize,
                         SMEM_BYTES);

    dim3 g1(4, NKC, 2);
    gemm_part<<<g1, TPB, SMEM_BYTES>>>(Wi, Wh, x, h);
    reduce_gates<<<64, 512>>>(Wib, Whb, c, out);
}